// round 2
// baseline (speedup 1.0000x reference)
#include <cuda_runtime.h>
#include <cstdint>

// Problem constants
#define BB 4
#define SS 1024
#define HH 1024
#define NHH 16
#define HDD 64
#define BH (BB*NHH)          // 64
#define CTX_ELEMS (BB*SS*HH)                 // 4,194,304
#define SCORES_ELEMS (BH*SS*SS)              // 67,108,864

// Scratch (static device memory — allocation-free rule)
__device__ float g_q[BH*SS*HDD];
__device__ float g_k[BH*SS*HDD];
__device__ float g_v[BH*SS*HDD];
__device__ float g_scores_fb[SCORES_ELEMS];  // fallback if scores not in d_out
__device__ float g_ctx_fb[CTX_ELEMS];        // fallback if ctx not in d_out

// ---------------------------------------------------------------------------
// Kernel 1: projection  Y = X @ W^T + b, written head-split to [BH][S][HD]
// X: [4096,1024], W: [1024,1024] (row n = output feature, k-contiguous)
// Tile: BM=128, BN=64, BK=16; 256 threads; per-thread 8x4
// ---------------------------------------------------------------------------
__global__ __launch_bounds__(256) void proj_kernel(
    const float* __restrict__ X, const float* __restrict__ W,
    const float* __restrict__ bias, float* __restrict__ out)
{
    __shared__ float As[16][132];   // [k][m] transposed, padded
    __shared__ float Bs[16][68];    // [k][n]

    const int tid = threadIdx.x;
    const int tx = tid & 15;        // n-group (0..15) -> 4 cols
    const int ty = tid >> 4;        // m-group (0..15) -> 8 rows
    const int n0 = blockIdx.x * 64;
    const int m0 = blockIdx.y * 128;

    float acc[8][4];
#pragma unroll
    for (int i = 0; i < 8; i++)
#pragma unroll
        for (int j = 0; j < 4; j++) acc[i][j] = 0.f;

    for (int k0 = 0; k0 < 1024; k0 += 16) {
        // A tile: 128 rows x 16 k  (512 float4, 2 per thread)
#pragma unroll
        for (int i = 0; i < 2; i++) {
            int f = tid + 256 * i;
            int row = f >> 2;
            int kq  = (f & 3) * 4;
            float4 v = *(const float4*)&X[(size_t)(m0 + row) * 1024 + k0 + kq];
            As[kq + 0][row] = v.x; As[kq + 1][row] = v.y;
            As[kq + 2][row] = v.z; As[kq + 3][row] = v.w;
        }
        // B tile: 64 rows x 16 k (256 float4, 1 per thread)
        {
            int row = tid >> 2;
            int kq  = (tid & 3) * 4;
            float4 v = *(const float4*)&W[(size_t)(n0 + row) * 1024 + k0 + kq];
            Bs[kq + 0][row] = v.x; Bs[kq + 1][row] = v.y;
            Bs[kq + 2][row] = v.z; Bs[kq + 3][row] = v.w;
        }
        __syncthreads();
#pragma unroll
        for (int kk = 0; kk < 16; kk++) {
            float4 a0 = *(const float4*)&As[kk][ty * 8];
            float4 a1 = *(const float4*)&As[kk][ty * 8 + 4];
            float4 b0 = *(const float4*)&Bs[kk][tx * 4];
            float a[8] = {a0.x, a0.y, a0.z, a0.w, a1.x, a1.y, a1.z, a1.w};
            float b[4] = {b0.x, b0.y, b0.z, b0.w};
#pragma unroll
            for (int i = 0; i < 8; i++)
#pragma unroll
                for (int j = 0; j < 4; j++)
                    acc[i][j] = fmaf(a[i], b[j], acc[i][j]);
        }
        __syncthreads();
    }

    // epilogue: add bias, scatter to [b*16+h][s][d] layout (d-contiguous float4)
    float4 bb = *(const float4*)&bias[n0 + tx * 4];
    const int h = n0 >> 6;                // n0 multiple of 64 -> fixed head
    const int d = (n0 & 63) + tx * 4;
#pragma unroll
    for (int i = 0; i < 8; i++) {
        int m = m0 + ty * 8 + i;
        int b = m >> 10, s = m & 1023;
        float4 o;
        o.x = acc[i][0] + bb.x;
        o.y = acc[i][1] + bb.y;
        o.z = acc[i][2] + bb.z;
        o.w = acc[i][3] + bb.w;
        *(float4*)&out[(((size_t)(b * NHH + h)) * SS + s) * HDD + d] = o;
    }
}

// ---------------------------------------------------------------------------
// Kernel 2: scores[s,t] = (q . k)/8 + (mask ? -9999 : 0), per head
// mask is 32-bit per element (bool widened to int32/float32): nonzero = masked
// ---------------------------------------------------------------------------
__global__ __launch_bounds__(256) void scores_kernel(
    const float* __restrict__ Q, const float* __restrict__ K,
    const int* __restrict__ mask, float* __restrict__ scores)
{
    __shared__ float As[16][132];
    __shared__ float Bs[16][68];

    const int tid = threadIdx.x;
    const int tx = tid & 15;
    const int ty = tid >> 4;
    const int bh = blockIdx.z;
    const int n0 = blockIdx.x * 64;    // t
    const int m0 = blockIdx.y * 128;   // s
    const float* Qb = Q + (size_t)bh * SS * HDD;
    const float* Kb = K + (size_t)bh * SS * HDD;

    float acc[8][4];
#pragma unroll
    for (int i = 0; i < 8; i++)
#pragma unroll
        for (int j = 0; j < 4; j++) acc[i][j] = 0.f;

    for (int k0 = 0; k0 < 64; k0 += 16) {
#pragma unroll
        for (int i = 0; i < 2; i++) {
            int f = tid + 256 * i;
            int row = f >> 2;
            int kq  = (f & 3) * 4;
            float4 v = *(const float4*)&Qb[(size_t)(m0 + row) * HDD + k0 + kq];
            As[kq + 0][row] = v.x; As[kq + 1][row] = v.y;
            As[kq + 2][row] = v.z; As[kq + 3][row] = v.w;
        }
        {
            int row = tid >> 2;
            int kq  = (tid & 3) * 4;
            float4 v = *(const float4*)&Kb[(size_t)(n0 + row) * HDD + k0 + kq];
            Bs[kq + 0][row] = v.x; Bs[kq + 1][row] = v.y;
            Bs[kq + 2][row] = v.z; Bs[kq + 3][row] = v.w;
        }
        __syncthreads();
#pragma unroll
        for (int kk = 0; kk < 16; kk++) {
            float4 a0 = *(const float4*)&As[kk][ty * 8];
            float4 a1 = *(const float4*)&As[kk][ty * 8 + 4];
            float4 b0 = *(const float4*)&Bs[kk][tx * 4];
            float a[8] = {a0.x, a0.y, a0.z, a0.w, a1.x, a1.y, a1.z, a1.w};
            float b[4] = {b0.x, b0.y, b0.z, b0.w};
#pragma unroll
            for (int i = 0; i < 8; i++)
#pragma unroll
                for (int j = 0; j < 4; j++)
                    acc[i][j] = fmaf(a[i], b[j], acc[i][j]);
        }
        __syncthreads();
    }

    const size_t rowbase = (size_t)bh * SS;
#pragma unroll
    for (int i = 0; i < 8; i++) {
        int m = m0 + ty * 8 + i;
        size_t off = (rowbase + m) * SS + n0 + tx * 4;
        int4 mk = *(const int4*)&mask[off];
        float4 o;
        o.x = acc[i][0] * 0.125f + (mk.x != 0 ? -9999.f : 0.f);
        o.y = acc[i][1] * 0.125f + (mk.y != 0 ? -9999.f : 0.f);
        o.z = acc[i][2] * 0.125f + (mk.z != 0 ? -9999.f : 0.f);
        o.w = acc[i][3] * 0.125f + (mk.w != 0 ? -9999.f : 0.f);
        *(float4*)&scores[off] = o;
    }
}

// ---------------------------------------------------------------------------
// Kernel 3: fused softmax + P@V.
// ---------------------------------------------------------------------------
__global__ __launch_bounds__(256) void attn_kernel(
    const float* __restrict__ scores, const float* __restrict__ V,
    float* __restrict__ ctx)
{
    __shared__ float Ps[64][68];
    __shared__ float Vs[64][68];
    __shared__ float smax[64];
    __shared__ float ssum[64];

    const int tid = threadIdx.x;
    const int bh = blockIdx.y;
    const int r0 = blockIdx.x * 64;
    const float* sb = scores + ((size_t)bh * SS + r0) * SS;

    // ---- phase 1: row stats (4 threads per row) ----
    {
        int lr = tid >> 2;
        int qq = tid & 3;
        const float* srow = sb + (size_t)lr * SS;
        float m = -3.0e38f;
        for (int c = qq * 4; c < SS; c += 16) {
            float4 v = *(const float4*)&srow[c];
            m = fmaxf(m, fmaxf(fmaxf(v.x, v.y), fmaxf(v.z, v.w)));
        }
        m = fmaxf(m, __shfl_xor_sync(0xffffffffu, m, 1));
        m = fmaxf(m, __shfl_xor_sync(0xffffffffu, m, 2));
        float s = 0.f;
        for (int c = qq * 4; c < SS; c += 16) {
            float4 v = *(const float4*)&srow[c];
            s += __expf(v.x - m) + __expf(v.y - m) + __expf(v.z - m) + __expf(v.w - m);
        }
        s += __shfl_xor_sync(0xffffffffu, s, 1);
        s += __shfl_xor_sync(0xffffffffu, s, 2);
        if (qq == 0) { smax[lr] = m; ssum[lr] = s; }
    }
    __syncthreads();

    // ---- phase 2: P@V ----
    const int tx = tid & 15;   // d-group
    const int ty = tid >> 4;   // row-group (16 groups x 4 rows)
    float acc[4][4];
#pragma unroll
    for (int i = 0; i < 4; i++)
#pragma unroll
        for (int j = 0; j < 4; j++) acc[i][j] = 0.f;

    const float* Vb = V + (size_t)bh * SS * HDD;

    for (int ct = 0; ct < 16; ct++) {
        int c0 = ct * 64;
#pragma unroll
        for (int i = 0; i < 4; i++) {
            int f = tid + 256 * i;
            int lr = f >> 4;
            int fc = (f & 15) * 4;
            float4 v = *(const float4*)&sb[(size_t)lr * SS + c0 + fc];
            float mr = smax[lr];
            float4 p;
            p.x = __expf(v.x - mr);
            p.y = __expf(v.y - mr);
            p.z = __expf(v.z - mr);
            p.w = __expf(v.w - mr);
            *(float4*)&Ps[lr][fc] = p;
        }
#pragma unroll
        for (int i = 0; i < 4; i++) {
            int f = tid + 256 * i;
            int vr = f >> 4;
            int vc = (f & 15) * 4;
            *(float4*)&Vs[vr][vc] = *(const float4*)&Vb[(size_t)(c0 + vr) * HDD + vc];
        }
        __syncthreads();
#pragma unroll 16
        for (int tt = 0; tt < 64; tt++) {
            float4 b4 = *(const float4*)&Vs[tt][tx * 4];
            float a0 = Ps[ty * 4 + 0][tt];
            float a1 = Ps[ty * 4 + 1][tt];
            float a2 = Ps[ty * 4 + 2][tt];
            float a3 = Ps[ty * 4 + 3][tt];
            acc[0][0] = fmaf(a0, b4.x, acc[0][0]);
            acc[0][1] = fmaf(a0, b4.y, acc[0][1]);
            acc[0][2] = fmaf(a0, b4.z, acc[0][2]);
            acc[0][3] = fmaf(a0, b4.w, acc[0][3]);
            acc[1][0] = fmaf(a1, b4.x, acc[1][0]);
            acc[1][1] = fmaf(a1, b4.y, acc[1][1]);
            acc[1][2] = fmaf(a1, b4.z, acc[1][2]);
            acc[1][3] = fmaf(a1, b4.w, acc[1][3]);
            acc[2][0] = fmaf(a2, b4.x, acc[2][0]);
            acc[2][1] = fmaf(a2, b4.y, acc[2][1]);
            acc[2][2] = fmaf(a2, b4.z, acc[2][2]);
            acc[2][3] = fmaf(a2, b4.w, acc[2][3]);
            acc[3][0] = fmaf(a3, b4.x, acc[3][0]);
            acc[3][1] = fmaf(a3, b4.y, acc[3][1]);
            acc[3][2] = fmaf(a3, b4.z, acc[3][2]);
            acc[3][3] = fmaf(a3, b4.w, acc[3][3]);
        }
        __syncthreads();
    }

    // epilogue: normalize, write ctx[b][s][h*64+d]
    const int b = bh >> 4;
    const int h = bh & 15;
#pragma unroll
    for (int i = 0; i < 4; i++) {
        int s = r0 + ty * 4 + i;
        float inv = 1.f / ssum[ty * 4 + i];
        float4 o;
        o.x = acc[i][0] * inv;
        o.y = acc[i][1] * inv;
        o.z = acc[i][2] * inv;
        o.w = acc[i][3] * inv;
        *(float4*)&ctx[((size_t)b * SS + s) * HH + h * HDD + tx * 4] = o;
    }
}

// ---------------------------------------------------------------------------
extern "C" void kernel_launch(void* const* d_in, const int* in_sizes, int n_in,
                              void* d_out, int out_size) {
    const float* qx = (const float*)d_in[0];
    const float* kx = (const float*)d_in[1];
    const float* vx = (const float*)d_in[2];
    const int* mask = (const int*)d_in[3];
    const float* Wq = (const float*)d_in[4];
    const float* bq = (const float*)d_in[5];
    const float* Wk = (const float*)d_in[6];
    const float* bk = (const float*)d_in[7];
    const float* Wv = (const float*)d_in[8];
    const float* bv = (const float*)d_in[9];

    float *qp, *kp, *vp, *sfb, *cfb;
    cudaGetSymbolAddress((void**)&qp, g_q);
    cudaGetSymbolAddress((void**)&kp, g_k);
    cudaGetSymbolAddress((void**)&vp, g_v);
    cudaGetSymbolAddress((void**)&sfb, g_scores_fb);
    cudaGetSymbolAddress((void**)&cfb, g_ctx_fb);

    float* ctx_out;
    float* scores_out;
    if (out_size >= CTX_ELEMS + SCORES_ELEMS) {
        ctx_out = (float*)d_out;
        scores_out = (float*)d_out + CTX_ELEMS;
    } else if (out_size == SCORES_ELEMS) {
        scores_out = (float*)d_out;
        ctx_out = cfb;
    } else {
        ctx_out = (float*)d_out;
        scores_out = sfb;
    }

    dim3 pg(16, 32);  // N/64, M/128
    proj_kernel<<<pg, 256>>>(qx, Wq, bq, qp);
    proj_kernel<<<pg, 256>>>(kx, Wk, bk, kp);
    proj_kernel<<<pg, 256>>>(vx, Wv, bv, vp);
    scores_kernel<<<dim3(16, 8, BH), 256>>>(qp, kp, mask, scores_out);
    attn_kernel<<<dim3(16, BH), 256>>>(scores_out, vp, ctx_out);
}

// round 4
// speedup vs baseline: 1.4589x; 1.4589x over previous
#include <cuda_runtime.h>
#include <cstdint>

// Problem constants
#define BB 4
#define SS 1024
#define HH 1024
#define NHH 16
#define HDD 64
#define BH (BB*NHH)          // 64
#define CTX_ELEMS (BB*SS*HH)                 // 4,194,304
#define SCORES_ELEMS (BH*SS*SS)              // 67,108,864

// Scratch (static device memory — allocation-free rule)
__device__ float g_q[BH*SS*HDD];
__device__ float g_k[BH*SS*HDD];
__device__ float g_v[BH*SS*HDD];
__device__ float g_scores_fb[SCORES_ELEMS];
__device__ float g_ctx_fb[CTX_ELEMS];

// ===========================================================================
// mma.sync tf32 helpers (baseline PTX, no sm_103a-only features)
// ===========================================================================
__device__ __forceinline__ uint32_t f2tf(float f) {
    uint32_t r;
    asm("cvt.rna.tf32.f32 %0, %1;" : "=r"(r) : "f"(f));
    return r;
}
__device__ __forceinline__ void mma_tf32(float* c,
    uint32_t a0, uint32_t a1, uint32_t a2, uint32_t a3,
    uint32_t b0, uint32_t b1)
{
    asm volatile(
        "mma.sync.aligned.m16n8k8.row.col.f32.tf32.tf32.f32 "
        "{%0,%1,%2,%3}, {%4,%5,%6,%7}, {%8,%9}, {%0,%1,%2,%3};"
        : "+f"(c[0]), "+f"(c[1]), "+f"(c[2]), "+f"(c[3])
        : "r"(a0), "r"(a1), "r"(a2), "r"(a3), "r"(b0), "r"(b1));
}

// smem tile stride (floats) for [k][m] layout: 136 % 32 == 8 ->
// fragment LDS banks = 8*k + m', conflict-free for k 0..3 x m 0..7.
#define TSTR 136
#define PBUF (32*TSTR)               // one 32-k-deep buffer (words)
#define MMA_SMEM_BYTES (4*PBUF*4)    // A(2 bufs) + B(2 bufs) = 69632 B

// ---------------------------------------------------------------------------
// Kernel 1: projection via mma.sync tf32.
// out[m,n] = sum_k X[m,k] * W[n,k] + bias[n], scattered head-split to
// [BH][S][HD].  CTA tile 128x128, K chunks of 32, reg-prefetch double buffer.
// 8 warps: warp (wm,wn) = (w&1, w>>1), warp tile 64(m) x 32(n).
// ---------------------------------------------------------------------------
__global__ __launch_bounds__(256) void proj_mma_kernel(
    const float* __restrict__ X, const float* __restrict__ W,
    const float* __restrict__ bias, float* __restrict__ out)
{
    extern __shared__ uint32_t sm[];
    uint32_t* As = sm;               // [2][32][TSTR]  (tf32 bits, [k][m])
    uint32_t* Bs = sm + 2*PBUF;      // [2][32][TSTR]  ([k][n])

    const int tid  = threadIdx.x;
    const int warp = tid >> 5, lane = tid & 31;
    const int wm = warp & 1, wn = warp >> 1;
    const int n0 = blockIdx.x * 128, m0 = blockIdx.y * 128;
    const int lrow = tid >> 1;           // 0..127
    const int cq   = (tid & 1) * 16;     // k sub-offset 0/16

    const float* Xr = X + (size_t)(m0 + lrow) * 1024 + cq;
    const float* Wr = W + (size_t)(n0 + lrow) * 1024 + cq;

    float c[4][4][4];
#pragma unroll
    for (int mt = 0; mt < 4; mt++)
#pragma unroll
        for (int nt = 0; nt < 4; nt++)
#pragma unroll
            for (int e = 0; e < 4; e++) c[mt][nt][e] = 0.f;

    const int r  = lane >> 2;
    const int ci = lane & 3;

    float4 pa[4], pb[4];
    // prefetch chunk 0
#pragma unroll
    for (int j = 0; j < 4; j++) {
        pa[j] = *(const float4*)(Xr + 4 * j);
        pb[j] = *(const float4*)(Wr + 4 * j);
    }
    // store chunk 0 into buf 0
    {
        uint32_t* da = As;
        uint32_t* db = Bs;
#pragma unroll
        for (int j = 0; j < 4; j++) {
            int k = cq + 4 * j;
            da[(k+0)*TSTR + lrow] = f2tf(pa[j].x);
            da[(k+1)*TSTR + lrow] = f2tf(pa[j].y);
            da[(k+2)*TSTR + lrow] = f2tf(pa[j].z);
            da[(k+3)*TSTR + lrow] = f2tf(pa[j].w);
            db[(k+0)*TSTR + lrow] = f2tf(pb[j].x);
            db[(k+1)*TSTR + lrow] = f2tf(pb[j].y);
            db[(k+2)*TSTR + lrow] = f2tf(pb[j].z);
            db[(k+3)*TSTR + lrow] = f2tf(pb[j].w);
        }
    }
    __syncthreads();

    for (int i = 0; i < 32; i++) {
        // issue global prefetch for chunk i+1 (overlaps with compute below)
        if (i + 1 < 32) {
            const float* xr = Xr + (i + 1) * 32;
            const float* wr = Wr + (i + 1) * 32;
#pragma unroll
            for (int j = 0; j < 4; j++) {
                pa[j] = *(const float4*)(xr + 4 * j);
                pb[j] = *(const float4*)(wr + 4 * j);
            }
        }
        // compute chunk i from buf i&1
        {
            uint32_t* Ab = As + (i & 1) * PBUF + wm * 64;
            uint32_t* Bb = Bs + (i & 1) * PBUF + wn * 32;
#pragma unroll
            for (int kf = 0; kf < 32; kf += 8) {
                uint32_t a[4][4], b[4][2];
#pragma unroll
                for (int mt = 0; mt < 4; mt++) {
                    a[mt][0] = Ab[(kf+ci  )*TSTR + mt*16 + r];
                    a[mt][1] = Ab[(kf+ci  )*TSTR + mt*16 + r + 8];
                    a[mt][2] = Ab[(kf+4+ci)*TSTR + mt*16 + r];
                    a[mt][3] = Ab[(kf+4+ci)*TSTR + mt*16 + r + 8];
                }
#pragma unroll
                for (int nt = 0; nt < 4; nt++) {
                    b[nt][0] = Bb[(kf+ci  )*TSTR + nt*8 + r];
                    b[nt][1] = Bb[(kf+4+ci)*TSTR + nt*8 + r];
                }
#pragma unroll
                for (int mt = 0; mt < 4; mt++)
#pragma unroll
                    for (int nt = 0; nt < 4; nt++)
                        mma_tf32(c[mt][nt], a[mt][0], a[mt][1], a[mt][2], a[mt][3],
                                 b[nt][0], b[nt][1]);
            }
        }
        // store prefetched chunk into the other buffer
        if (i + 1 < 32) {
            uint32_t* da = As + ((i + 1) & 1) * PBUF;
            uint32_t* db = Bs + ((i + 1) & 1) * PBUF;
#pragma unroll
            for (int j = 0; j < 4; j++) {
                int k = cq + 4 * j;
                da[(k+0)*TSTR + lrow] = f2tf(pa[j].x);
                da[(k+1)*TSTR + lrow] = f2tf(pa[j].y);
                da[(k+2)*TSTR + lrow] = f2tf(pa[j].z);
                da[(k+3)*TSTR + lrow] = f2tf(pa[j].w);
                db[(k+0)*TSTR + lrow] = f2tf(pb[j].x);
                db[(k+1)*TSTR + lrow] = f2tf(pb[j].y);
                db[(k+2)*TSTR + lrow] = f2tf(pb[j].z);
                db[(k+3)*TSTR + lrow] = f2tf(pb[j].w);
            }
            __syncthreads();
        }
    }

    // epilogue: bias + head-split scatter
    const int nb   = n0 + wn * 32;       // multiple of 32
    const int head = nb >> 6;
    const int d0   = nb & 63;            // 0 or 32
#pragma unroll
    for (int mt = 0; mt < 4; mt++) {
        int m = m0 + wm * 64 + mt * 16 + r;
        int bidx = m >> 10, s = m & 1023;
        float* po = out + (((size_t)(bidx * NHH + head)) * SS + s) * HDD + d0;
#pragma unroll
        for (int nt = 0; nt < 4; nt++) {
            int dn = nt * 8 + ci * 2;
            float2 bb = *(const float2*)&bias[nb + dn];
            float2 o0, o1;
            o0.x = c[mt][nt][0] + bb.x;  o0.y = c[mt][nt][1] + bb.y;
            o1.x = c[mt][nt][2] + bb.x;  o1.y = c[mt][nt][3] + bb.y;
            *(float2*)&po[dn]          = o0;   // row m
            *(float2*)&po[dn + 8*HDD]  = o1;   // row m+8 (same b, s+8)
        }
    }
}

// ---------------------------------------------------------------------------
// Kernel 2: scores via mma.sync tf32.
// scores[s,t] = (q.k)/8 + (mask?-9999:0). CTA 128(s)x128(t) per head, K=64.
// ---------------------------------------------------------------------------
__global__ __launch_bounds__(256) void scores_mma_kernel(
    const float* __restrict__ Q, const float* __restrict__ K,
    const int* __restrict__ mask, float* __restrict__ scores)
{
    extern __shared__ uint32_t sm[];
    uint32_t* Qs = sm;               // [64][TSTR]  ([k][s])
    uint32_t* Ks = sm + 64*TSTR;     // [64][TSTR]  ([k][t])

    const int tid  = threadIdx.x;
    const int warp = tid >> 5, lane = tid & 31;
    const int wm = warp & 1, wn = warp >> 1;
    const int bh = blockIdx.z;
    const int n0 = blockIdx.x * 128, m0 = blockIdx.y * 128;
    const float* Qb = Q + (size_t)bh * SS * HDD;
    const float* Kb = K + (size_t)bh * SS * HDD;

    const int lrow = tid >> 1;
    const int cq   = (tid & 1) * 32;
    const float* qr = Qb + (size_t)(m0 + lrow) * HDD + cq;
    const float* kr = Kb + (size_t)(n0 + lrow) * HDD + cq;
#pragma unroll
    for (int j = 0; j < 8; j++) {
        float4 v = *(const float4*)(qr + 4 * j);
        float4 w = *(const float4*)(kr + 4 * j);
        int k = cq + 4 * j;
        Qs[(k+0)*TSTR + lrow] = f2tf(v.x);
        Qs[(k+1)*TSTR + lrow] = f2tf(v.y);
        Qs[(k+2)*TSTR + lrow] = f2tf(v.z);
        Qs[(k+3)*TSTR + lrow] = f2tf(v.w);
        Ks[(k+0)*TSTR + lrow] = f2tf(w.x);
        Ks[(k+1)*TSTR + lrow] = f2tf(w.y);
        Ks[(k+2)*TSTR + lrow] = f2tf(w.z);
        Ks[(k+3)*TSTR + lrow] = f2tf(w.w);
    }
    __syncthreads();

    float c[4][4][4];
#pragma unroll
    for (int mt = 0; mt < 4; mt++)
#pragma unroll
        for (int nt = 0; nt < 4; nt++)
#pragma unroll
            for (int e = 0; e < 4; e++) c[mt][nt][e] = 0.f;

    const int r  = lane >> 2;
    const int ci = lane & 3;
    uint32_t* Ab = Qs + wm * 64;
    uint32_t* Bb = Ks + wn * 32;
#pragma unroll
    for (int kf = 0; kf < 64; kf += 8) {
        uint32_t a[4][4], b[4][2];
#pragma unroll
        for (int mt = 0; mt < 4; mt++) {
            a[mt][0] = Ab[(kf+ci  )*TSTR + mt*16 + r];
            a[mt][1] = Ab[(kf+ci  )*TSTR + mt*16 + r + 8];
            a[mt][2] = Ab[(kf+4+ci)*TSTR + mt*16 + r];
            a[mt][3] = Ab[(kf+4+ci)*TSTR + mt*16 + r + 8];
        }
#pragma unroll
        for (int nt = 0; nt < 4; nt++) {
            b[nt][0] = Bb[(kf+ci  )*TSTR + nt*8 + r];
            b[nt][1] = Bb[(kf+4+ci)*TSTR + nt*8 + r];
        }
#pragma unroll
        for (int mt = 0; mt < 4; mt++)
#pragma unroll
            for (int nt = 0; nt < 4; nt++)
                mma_tf32(c[mt][nt], a[mt][0], a[mt][1], a[mt][2], a[mt][3],
                         b[nt][0], b[nt][1]);
    }

    // epilogue: scale + mask + store
#pragma unroll
    for (int mt = 0; mt < 4; mt++) {
        int s = m0 + wm * 64 + mt * 16 + r;
        size_t rowoff = ((size_t)bh * SS + s) * SS;
#pragma unroll
        for (int nt = 0; nt < 4; nt++) {
            int t = n0 + wn * 32 + nt * 8 + ci * 2;
            size_t off0 = rowoff + t;
            size_t off1 = off0 + 8 * SS;
            int2 mk0 = *(const int2*)&mask[off0];
            int2 mk1 = *(const int2*)&mask[off1];
            float2 o0, o1;
            o0.x = c[mt][nt][0] * 0.125f + (mk0.x != 0 ? -9999.f : 0.f);
            o0.y = c[mt][nt][1] * 0.125f + (mk0.y != 0 ? -9999.f : 0.f);
            o1.x = c[mt][nt][2] * 0.125f + (mk1.x != 0 ? -9999.f : 0.f);
            o1.y = c[mt][nt][3] * 0.125f + (mk1.y != 0 ? -9999.f : 0.f);
            *(float2*)&scores[off0] = o0;
            *(float2*)&scores[off1] = o1;
        }
    }
}

// ---------------------------------------------------------------------------
// Kernel 3: fused softmax + P@V (unchanged from round 2)
// ---------------------------------------------------------------------------
__global__ __launch_bounds__(256) void attn_kernel(
    const float* __restrict__ scores, const float* __restrict__ V,
    float* __restrict__ ctx)
{
    __shared__ float Ps[64][68];
    __shared__ float Vs[64][68];
    __shared__ float smax[64];
    __shared__ float ssum[64];

    const int tid = threadIdx.x;
    const int bh = blockIdx.y;
    const int r0 = blockIdx.x * 64;
    const float* sb = scores + ((size_t)bh * SS + r0) * SS;

    {
        int lr = tid >> 2;
        int qq = tid & 3;
        const float* srow = sb + (size_t)lr * SS;
        float m = -3.0e38f;
        for (int c = qq * 4; c < SS; c += 16) {
            float4 v = *(const float4*)&srow[c];
            m = fmaxf(m, fmaxf(fmaxf(v.x, v.y), fmaxf(v.z, v.w)));
        }
        m = fmaxf(m, __shfl_xor_sync(0xffffffffu, m, 1));
        m = fmaxf(m, __shfl_xor_sync(0xffffffffu, m, 2));
        float s = 0.f;
        for (int c = qq * 4; c < SS; c += 16) {
            float4 v = *(const float4*)&srow[c];
            s += __expf(v.x - m) + __expf(v.y - m) + __expf(v.z - m) + __expf(v.w - m);
        }
        s += __shfl_xor_sync(0xffffffffu, s, 1);
        s += __shfl_xor_sync(0xffffffffu, s, 2);
        if (qq == 0) { smax[lr] = m; ssum[lr] = s; }
    }
    __syncthreads();

    const int tx = tid & 15;
    const int ty = tid >> 4;
    float acc[4][4];
#pragma unroll
    for (int i = 0; i < 4; i++)
#pragma unroll
        for (int j = 0; j < 4; j++) acc[i][j] = 0.f;

    const float* Vb = V + (size_t)bh * SS * HDD;

    for (int ct = 0; ct < 16; ct++) {
        int c0 = ct * 64;
#pragma unroll
        for (int i = 0; i < 4; i++) {
            int f = tid + 256 * i;
            int lr = f >> 4;
            int fc = (f & 15) * 4;
            float4 v = *(const float4*)&sb[(size_t)lr * SS + c0 + fc];
            float mr = smax[lr];
            float4 p;
            p.x = __expf(v.x - mr);
            p.y = __expf(v.y - mr);
            p.z = __expf(v.z - mr);
            p.w = __expf(v.w - mr);
            *(float4*)&Ps[lr][fc] = p;
        }
#pragma unroll
        for (int i = 0; i < 4; i++) {
            int f = tid + 256 * i;
            int vr = f >> 4;
            int vc = (f & 15) * 4;
            *(float4*)&Vs[vr][vc] = *(const float4*)&Vb[(size_t)(c0 + vr) * HDD + vc];
        }
        __syncthreads();
#pragma unroll 16
        for (int tt = 0; tt < 64; tt++) {
            float4 b4 = *(const float4*)&Vs[tt][tx * 4];
            float a0 = Ps[ty * 4 + 0][tt];
            float a1 = Ps[ty * 4 + 1][tt];
            float a2 = Ps[ty * 4 + 2][tt];
            float a3 = Ps[ty * 4 + 3][tt];
            acc[0][0] = fmaf(a0, b4.x, acc[0][0]);
            acc[0][1] = fmaf(a0, b4.y, acc[0][1]);
            acc[0][2] = fmaf(a0, b4.z, acc[0][2]);
            acc[0][3] = fmaf(a0, b4.w, acc[0][3]);
            acc[1][0] = fmaf(a1, b4.x, acc[1][0]);
            acc[1][1] = fmaf(a1, b4.y, acc[1][1]);
            acc[1][2] = fmaf(a1, b4.z, acc[1][2]);
            acc[1][3] = fmaf(a1, b4.w, acc[1][3]);
            acc[2][0] = fmaf(a2, b4.x, acc[2][0]);
            acc[2][1] = fmaf(a2, b4.y, acc[2][1]);
            acc[2][2] = fmaf(a2, b4.z, acc[2][2]);
            acc[2][3] = fmaf(a2, b4.w, acc[2][3]);
            acc[3][0] = fmaf(a3, b4.x, acc[3][0]);
            acc[3][1] = fmaf(a3, b4.y, acc[3][1]);
            acc[3][2] = fmaf(a3, b4.z, acc[3][2]);
            acc[3][3] = fmaf(a3, b4.w, acc[3][3]);
        }
        __syncthreads();
    }

    const int b = bh >> 4;
    const int h = bh & 15;
#pragma unroll
    for (int i = 0; i < 4; i++) {
        int s = r0 + ty * 4 + i;
        float inv = 1.f / ssum[ty * 4 + i];
        float4 o;
        o.x = acc[i][0] * inv;
        o.y = acc[i][1] * inv;
        o.z = acc[i][2] * inv;
        o.w = acc[i][3] * inv;
        *(float4*)&ctx[((size_t)b * SS + s) * HH + h * HDD + tx * 4] = o;
    }
}

// ---------------------------------------------------------------------------
extern "C" void kernel_launch(void* const* d_in, const int* in_sizes, int n_in,
                              void* d_out, int out_size) {
    const float* qx = (const float*)d_in[0];
    const float* kx = (const float*)d_in[1];
    const float* vx = (const float*)d_in[2];
    const int* mask = (const int*)d_in[3];
    const float* Wq = (const float*)d_in[4];
    const float* bq = (const float*)d_in[5];
    const float* Wk = (const float*)d_in[6];
    const float* bk = (const float*)d_in[7];
    const float* Wv = (const float*)d_in[8];
    const float* bv = (const float*)d_in[9];

    float *qp, *kp, *vp, *sfb, *cfb;
    cudaGetSymbolAddress((void**)&qp, g_q);
    cudaGetSymbolAddress((void**)&kp, g_k);
    cudaGetSymbolAddress((void**)&vp, g_v);
    cudaGetSymbolAddress((void**)&sfb, g_scores_fb);
    cudaGetSymbolAddress((void**)&cfb, g_ctx_fb);

    float* ctx_out;
    float* scores_out;
    if (out_size >= CTX_ELEMS + SCORES_ELEMS) {
        ctx_out = (float*)d_out;
        scores_out = (float*)d_out + CTX_ELEMS;
    } else if (out_size == SCORES_ELEMS) {
        scores_out = (float*)d_out;
        ctx_out = cfb;
    } else {
        ctx_out = (float*)d_out;
        scores_out = sfb;
    }

    cudaFuncSetAttribute(proj_mma_kernel,
                         cudaFuncAttributeMaxDynamicSharedMemorySize, MMA_SMEM_BYTES);
    cudaFuncSetAttribute(scores_mma_kernel,
                         cudaFuncAttributeMaxDynamicSharedMemorySize, MMA_SMEM_BYTES);

    dim3 pg(8, 32);  // N/128, M/128
    proj_mma_kernel<<<pg, 256, MMA_SMEM_BYTES>>>(qx, Wq, bq, qp);
    proj_mma_kernel<<<pg, 256, MMA_SMEM_BYTES>>>(kx, Wk, bk, kp);
    proj_mma_kernel<<<pg, 256, MMA_SMEM_BYTES>>>(vx, Wv, bv, vp);
    scores_mma_kernel<<<dim3(8, 8, BH), 256, MMA_SMEM_BYTES>>>(qp, kp, mask, scores_out);
    attn_kernel<<<dim3(16, BH), 256>>>(scores_out, vp, ctx_out);
}

// round 7
// speedup vs baseline: 1.7698x; 1.2131x over previous
#include <cuda_runtime.h>
#include <cstdint>

// Problem constants
#define BB 4
#define SS 1024
#define HH 1024
#define NHH 16
#define HDD 64
#define BH (BB*NHH)          // 64
#define CTX_ELEMS (BB*SS*HH)                 // 4,194,304
#define SCORES_ELEMS (BH*SS*SS)              // 67,108,864

// Scratch (static device memory — allocation-free rule)
__device__ float g_q[BH*SS*HDD];
__device__ float g_k[BH*SS*HDD];
__device__ float g_v[BH*SS*HDD];
__device__ float g_scores_fb[SCORES_ELEMS];
__device__ float g_ctx_fb[CTX_ELEMS];

// ===========================================================================
// mma.sync tf32 helpers (baseline PTX; tcgen05 rejected by sm_103 target)
// ===========================================================================
__device__ __forceinline__ uint32_t f2tf(float f) {
    uint32_t r;
    asm("cvt.rna.tf32.f32 %0, %1;" : "=r"(r) : "f"(f));
    return r;
}
__device__ __forceinline__ void mma_tf32(float* c,
    uint32_t a0, uint32_t a1, uint32_t a2, uint32_t a3,
    uint32_t b0, uint32_t b1)
{
    asm volatile(
        "mma.sync.aligned.m16n8k8.row.col.f32.tf32.tf32.f32 "
        "{%0,%1,%2,%3}, {%4,%5,%6,%7}, {%8,%9}, {%0,%1,%2,%3};"
        : "+f"(c[0]), "+f"(c[1]), "+f"(c[2]), "+f"(c[3])
        : "r"(a0), "r"(a1), "r"(a2), "r"(a3), "r"(b0), "r"(b1));
}

#define TSTR 136   // [k][m] tile stride: conflict-free fragment LDS
#define VSTR 72    // V tile [t][d] stride
#define PBUF (32*TSTR)
#define MMA_SMEM_BYTES (4*PBUF*4)

// fused kernel smem layout (words)
#define FQ_OFF  0
#define FK_OFF  (64*TSTR)                 // 8704
#define FP_OFF  (FK_OFF + 64*TSTR)        // 17408
#define FV_OFF  (FP_OFF + 128*TSTR)       // 34816
#define FR_OFF  (FV_OFF + 128*VSTR)       // 44032
#define FUSED_SMEM_BYTES ((FR_OFF + 256) * 4)   // 177,152 B

// ---------------------------------------------------------------------------
// Kernel 1: projection via mma.sync tf32 (unchanged from round 4)
// ---------------------------------------------------------------------------
__global__ __launch_bounds__(256) void proj_mma_kernel(
    const float* __restrict__ X, const float* __restrict__ W,
    const float* __restrict__ bias, float* __restrict__ out)
{
    extern __shared__ uint32_t sm[];
    uint32_t* As = sm;
    uint32_t* Bs = sm + 2*PBUF;

    const int tid  = threadIdx.x;
    const int warp = tid >> 5, lane = tid & 31;
    const int wm = warp & 1, wn = warp >> 1;
    const int n0 = blockIdx.x * 128, m0 = blockIdx.y * 128;
    const int lrow = tid >> 1;
    const int cq   = (tid & 1) * 16;

    const float* Xr = X + (size_t)(m0 + lrow) * 1024 + cq;
    const float* Wr = W + (size_t)(n0 + lrow) * 1024 + cq;

    float c[4][4][4];
#pragma unroll
    for (int mt = 0; mt < 4; mt++)
#pragma unroll
        for (int nt = 0; nt < 4; nt++)
#pragma unroll
            for (int e = 0; e < 4; e++) c[mt][nt][e] = 0.f;

    const int r  = lane >> 2;
    const int ci = lane & 3;

    float4 pa[4], pb[4];
#pragma unroll
    for (int j = 0; j < 4; j++) {
        pa[j] = *(const float4*)(Xr + 4 * j);
        pb[j] = *(const float4*)(Wr + 4 * j);
    }
    {
        uint32_t* da = As;
        uint32_t* db = Bs;
#pragma unroll
        for (int j = 0; j < 4; j++) {
            int k = cq + 4 * j;
            da[(k+0)*TSTR + lrow] = f2tf(pa[j].x);
            da[(k+1)*TSTR + lrow] = f2tf(pa[j].y);
            da[(k+2)*TSTR + lrow] = f2tf(pa[j].z);
            da[(k+3)*TSTR + lrow] = f2tf(pa[j].w);
            db[(k+0)*TSTR + lrow] = f2tf(pb[j].x);
            db[(k+1)*TSTR + lrow] = f2tf(pb[j].y);
            db[(k+2)*TSTR + lrow] = f2tf(pb[j].z);
            db[(k+3)*TSTR + lrow] = f2tf(pb[j].w);
        }
    }
    __syncthreads();

    for (int i = 0; i < 32; i++) {
        if (i + 1 < 32) {
            const float* xr = Xr + (i + 1) * 32;
            const float* wr = Wr + (i + 1) * 32;
#pragma unroll
            for (int j = 0; j < 4; j++) {
                pa[j] = *(const float4*)(xr + 4 * j);
                pb[j] = *(const float4*)(wr + 4 * j);
            }
        }
        {
            uint32_t* Ab = As + (i & 1) * PBUF + wm * 64;
            uint32_t* Bb = Bs + (i & 1) * PBUF + wn * 32;
#pragma unroll
            for (int kf = 0; kf < 32; kf += 8) {
                uint32_t a[4][4], b[4][2];
#pragma unroll
                for (int mt = 0; mt < 4; mt++) {
                    a[mt][0] = Ab[(kf+ci  )*TSTR + mt*16 + r];
                    a[mt][1] = Ab[(kf+ci  )*TSTR + mt*16 + r + 8];
                    a[mt][2] = Ab[(kf+4+ci)*TSTR + mt*16 + r];
                    a[mt][3] = Ab[(kf+4+ci)*TSTR + mt*16 + r + 8];
                }
#pragma unroll
                for (int nt = 0; nt < 4; nt++) {
                    b[nt][0] = Bb[(kf+ci  )*TSTR + nt*8 + r];
                    b[nt][1] = Bb[(kf+4+ci)*TSTR + nt*8 + r];
                }
#pragma unroll
                for (int mt = 0; mt < 4; mt++)
#pragma unroll
                    for (int nt = 0; nt < 4; nt++)
                        mma_tf32(c[mt][nt], a[mt][0], a[mt][1], a[mt][2], a[mt][3],
                                 b[nt][0], b[nt][1]);
            }
        }
        if (i + 1 < 32) {
            uint32_t* da = As + ((i + 1) & 1) * PBUF;
            uint32_t* db = Bs + ((i + 1) & 1) * PBUF;
#pragma unroll
            for (int j = 0; j < 4; j++) {
                int k = cq + 4 * j;
                da[(k+0)*TSTR + lrow] = f2tf(pa[j].x);
                da[(k+1)*TSTR + lrow] = f2tf(pa[j].y);
                da[(k+2)*TSTR + lrow] = f2tf(pa[j].z);
                da[(k+3)*TSTR + lrow] = f2tf(pa[j].w);
                db[(k+0)*TSTR + lrow] = f2tf(pb[j].x);
                db[(k+1)*TSTR + lrow] = f2tf(pb[j].y);
                db[(k+2)*TSTR + lrow] = f2tf(pb[j].z);
                db[(k+3)*TSTR + lrow] = f2tf(pb[j].w);
            }
            __syncthreads();
        }
    }

    const int nb   = n0 + wn * 32;
    const int head = nb >> 6;
    const int d0   = nb & 63;
#pragma unroll
    for (int mt = 0; mt < 4; mt++) {
        int m = m0 + wm * 64 + mt * 16 + r;
        int bidx = m >> 10, s = m & 1023;
        float* po = out + (((size_t)(bidx * NHH + head)) * SS + s) * HDD + d0;
#pragma unroll
        for (int nt = 0; nt < 4; nt++) {
            int dn = nt * 8 + ci * 2;
            float2 bb = *(const float2*)&bias[nb + dn];
            float2 o0, o1;
            o0.x = c[mt][nt][0] + bb.x;  o0.y = c[mt][nt][1] + bb.y;
            o1.x = c[mt][nt][2] + bb.x;  o1.y = c[mt][nt][3] + bb.y;
            *(float2*)&po[dn]          = o0;
            *(float2*)&po[dn + 8*HDD]  = o1;
        }
    }
}

// ---------------------------------------------------------------------------
// Kernel 2 (fused): scores + softmax (no max-subtraction) + P@V, flash-style.
// CTA = (head bh, 128-row s-tile); loops 8 t-tiles of 128.
// Writes scores (mandatory output) once, accumulates PV in registers.
// ---------------------------------------------------------------------------
__global__ __launch_bounds__(256) void fused_attn_kernel(
    const float* __restrict__ Q, const float* __restrict__ K,
    const float* __restrict__ V, const int* __restrict__ mask,
    float* __restrict__ scores, float* __restrict__ ctx)
{
    extern __shared__ uint32_t sm[];
    uint32_t* Qs = sm + FQ_OFF;    // [64 d][TSTR] tf32
    uint32_t* Ks = sm + FK_OFF;    // [64 d][TSTR]
    uint32_t* Ps = sm + FP_OFF;    // [128 t][TSTR] tf32 exp values
    uint32_t* Vs = sm + FV_OFF;    // [128 t][VSTR]
    float*    Rs = (float*)(sm + FR_OFF);   // [2][128]

    const int tid  = threadIdx.x;
    const int warp = tid >> 5, lane = tid & 31;
    const int r  = lane >> 2;
    const int ci = lane & 3;
    const int bh = blockIdx.y;
    const int s0 = blockIdx.x * 128;

    const float* Qb = Q + (size_t)bh * SS * HDD;
    const float* Kb = K + (size_t)bh * SS * HDD;
    const float* Vb = V + (size_t)bh * SS * HDD;

    const int lrow = tid >> 1;          // 0..127
    const int cq   = (tid & 1) * 32;    // d half

    // load Q tile (once): Qs[d][s]
    {
        const float* qr = Qb + (size_t)(s0 + lrow) * HDD + cq;
#pragma unroll
        for (int j = 0; j < 8; j++) {
            float4 v = *(const float4*)(qr + 4 * j);
            int k = cq + 4 * j;
            Qs[(k+0)*TSTR + lrow] = f2tf(v.x);
            Qs[(k+1)*TSTR + lrow] = f2tf(v.y);
            Qs[(k+2)*TSTR + lrow] = f2tf(v.z);
            Qs[(k+3)*TSTR + lrow] = f2tf(v.w);
        }
    }

    // S-phase warp map: wm(2) x wn(4) -> 64s x 32t
    const int wm = warp & 1, wn = warp >> 1;
    // PV-phase warp map: wm2(2) x wn2(4) -> 64s x 16d
    const int wm2 = warp & 1, wn2 = warp >> 1;

    float o[4][2][4];   // PV acc: 4 mt2 (16s each) x 2 nt2 (8d each)
#pragma unroll
    for (int mt = 0; mt < 4; mt++)
#pragma unroll
        for (int nt = 0; nt < 2; nt++)
#pragma unroll
            for (int e = 0; e < 4; e++) o[mt][nt][e] = 0.f;

    const int sloc = tid & 127;
    const int half = tid >> 7;
    float rsum_local = 0.f;

    for (int tt = 0; tt < 8; tt++) {
        const int t0 = tt * 128;
        __syncthreads();   // Ks/Vs/Ps reuse barrier
        // load K,V tiles (rows t0..t0+127)
        {
            const float* kr = Kb + (size_t)(t0 + lrow) * HDD + cq;
            const float* vr = Vb + (size_t)(t0 + lrow) * HDD + cq;
#pragma unroll
            for (int j = 0; j < 8; j++) {
                float4 kv = *(const float4*)(kr + 4 * j);
                float4 vv = *(const float4*)(vr + 4 * j);
                int k = cq + 4 * j;
                Ks[(k+0)*TSTR + lrow] = f2tf(kv.x);
                Ks[(k+1)*TSTR + lrow] = f2tf(kv.y);
                Ks[(k+2)*TSTR + lrow] = f2tf(kv.z);
                Ks[(k+3)*TSTR + lrow] = f2tf(kv.w);
                Vs[lrow*VSTR + k+0] = f2tf(vv.x);
                Vs[lrow*VSTR + k+1] = f2tf(vv.y);
                Vs[lrow*VSTR + k+2] = f2tf(vv.z);
                Vs[lrow*VSTR + k+3] = f2tf(vv.w);
            }
        }
        __syncthreads();

        // ---- S = Q K^T for this tile ----
        float c[4][4][4];
#pragma unroll
        for (int mt = 0; mt < 4; mt++)
#pragma unroll
            for (int nt = 0; nt < 4; nt++)
#pragma unroll
                for (int e = 0; e < 4; e++) c[mt][nt][e] = 0.f;

        uint32_t* Ab = Qs + wm * 64;
        uint32_t* Bb = Ks + wn * 32;
#pragma unroll
        for (int kf = 0; kf < 64; kf += 8) {
            uint32_t a[4][4], b[4][2];
#pragma unroll
            for (int mt = 0; mt < 4; mt++) {
                a[mt][0] = Ab[(kf+ci  )*TSTR + mt*16 + r];
                a[mt][1] = Ab[(kf+ci  )*TSTR + mt*16 + r + 8];
                a[mt][2] = Ab[(kf+4+ci)*TSTR + mt*16 + r];
                a[mt][3] = Ab[(kf+4+ci)*TSTR + mt*16 + r + 8];
            }
#pragma unroll
            for (int nt = 0; nt < 4; nt++) {
                b[nt][0] = Bb[(kf+ci  )*TSTR + nt*8 + r];
                b[nt][1] = Bb[(kf+4+ci)*TSTR + nt*8 + r];
            }
#pragma unroll
            for (int mt = 0; mt < 4; mt++)
#pragma unroll
                for (int nt = 0; nt < 4; nt++)
                    mma_tf32(c[mt][nt], a[mt][0], a[mt][1], a[mt][2], a[mt][3],
                             b[nt][0], b[nt][1]);
        }

        // ---- epilogue: mask+scale, write scores, exp -> Ps ----
#pragma unroll
        for (int mt = 0; mt < 4; mt++) {
            int s = wm * 64 + mt * 16 + r;
            size_t rowoff = ((size_t)bh * SS + (s0 + s)) * SS;
#pragma unroll
            for (int nt = 0; nt < 4; nt++) {
                int lt = wn * 32 + nt * 8 + ci * 2;
                size_t off0 = rowoff + t0 + lt;
                size_t off1 = off0 + 8 * SS;
                int2 mk0 = *(const int2*)&mask[off0];
                int2 mk1 = *(const int2*)&mask[off1];
                float2 sv0, sv1;
                sv0.x = c[mt][nt][0] * 0.125f + (mk0.x != 0 ? -9999.f : 0.f);
                sv0.y = c[mt][nt][1] * 0.125f + (mk0.y != 0 ? -9999.f : 0.f);
                sv1.x = c[mt][nt][2] * 0.125f + (mk1.x != 0 ? -9999.f : 0.f);
                sv1.y = c[mt][nt][3] * 0.125f + (mk1.y != 0 ? -9999.f : 0.f);
                *(float2*)&scores[off0] = sv0;
                *(float2*)&scores[off1] = sv1;
                Ps[(lt  )*TSTR + s    ] = f2tf(__expf(sv0.x));
                Ps[(lt+1)*TSTR + s    ] = f2tf(__expf(sv0.y));
                Ps[(lt  )*TSTR + s + 8] = f2tf(__expf(sv1.x));
                Ps[(lt+1)*TSTR + s + 8] = f2tf(__expf(sv1.y));
            }
        }
        __syncthreads();

        // ---- rowsum partial (from tf32 P, consistent with PV numerator) ----
        {
            float ssum = 0.f;
            const uint32_t* pp = Ps + (half * 64) * TSTR + sloc;
#pragma unroll 16
            for (int t = 0; t < 64; t++)
                ssum += __uint_as_float(pp[t * TSTR]);
            rsum_local += ssum;
        }

        // ---- PV accumulate: o += P(128s x 128t) @ V(128t x 64d) ----
        {
            uint32_t* Pb = Ps + wm2 * 64;
            uint32_t* Vbk = Vs + wn2 * 16;
#pragma unroll
            for (int kf = 0; kf < 128; kf += 8) {
                uint32_t a[4][4], b[2][2];
#pragma unroll
                for (int mt = 0; mt < 4; mt++) {
                    a[mt][0] = Pb[(kf+ci  )*TSTR + mt*16 + r];
                    a[mt][1] = Pb[(kf+ci  )*TSTR + mt*16 + r + 8];
                    a[mt][2] = Pb[(kf+4+ci)*TSTR + mt*16 + r];
                    a[mt][3] = Pb[(kf+4+ci)*TSTR + mt*16 + r + 8];
                }
#pragma unroll
                for (int nt = 0; nt < 2; nt++) {
                    b[nt][0] = Vbk[(kf+ci  )*VSTR + nt*8 + r];
                    b[nt][1] = Vbk[(kf+4+ci)*VSTR + nt*8 + r];
                }
#pragma unroll
                for (int mt = 0; mt < 4; mt++)
#pragma unroll
                    for (int nt = 0; nt < 2; nt++)
                        mma_tf32(o[mt][nt], a[mt][0], a[mt][1], a[mt][2], a[mt][3],
                                 b[nt][0], b[nt][1]);
            }
        }
    }

    // combine rowsums
    Rs[half * 128 + sloc] = rsum_local;
    __syncthreads();

    // final: normalize, write ctx [b][s][h*64+d]
    const int bidx = bh >> 4;
    const int h = bh & 15;
#pragma unroll
    for (int mt = 0; mt < 4; mt++) {
        int s = wm2 * 64 + mt * 16 + r;
        float inv0 = 1.f / (Rs[s] + Rs[128 + s]);
        float inv1 = 1.f / (Rs[s + 8] + Rs[128 + s + 8]);
        float* po0 = ctx + ((size_t)bidx * SS + (s0 + s)) * HH + h * HDD;
        float* po1 = po0 + 8 * HH;
#pragma unroll
        for (int nt = 0; nt < 2; nt++) {
            int d = wn2 * 16 + nt * 8 + ci * 2;
            float2 w0, w1;
            w0.x = o[mt][nt][0] * inv0;  w0.y = o[mt][nt][1] * inv0;
            w1.x = o[mt][nt][2] * inv1;  w1.y = o[mt][nt][3] * inv1;
            *(float2*)&po0[d] = w0;
            *(float2*)&po1[d] = w1;
        }
    }
}

// ---------------------------------------------------------------------------
extern "C" void kernel_launch(void* const* d_in, const int* in_sizes, int n_in,
                              void* d_out, int out_size) {
    const float* qx = (const float*)d_in[0];
    const float* kx = (const float*)d_in[1];
    const float* vx = (const float*)d_in[2];
    const int* mask = (const int*)d_in[3];
    const float* Wq = (const float*)d_in[4];
    const float* bq = (const float*)d_in[5];
    const float* Wk = (const float*)d_in[6];
    const float* bk = (const float*)d_in[7];
    const float* Wv = (const float*)d_in[8];
    const float* bv = (const float*)d_in[9];

    float *qp, *kp, *vp, *sfb, *cfb;
    cudaGetSymbolAddress((void**)&qp, g_q);
    cudaGetSymbolAddress((void**)&kp, g_k);
    cudaGetSymbolAddress((void**)&vp, g_v);
    cudaGetSymbolAddress((void**)&sfb, g_scores_fb);
    cudaGetSymbolAddress((void**)&cfb, g_ctx_fb);

    float* ctx_out;
    float* scores_out;
    if (out_size >= CTX_ELEMS + SCORES_ELEMS) {
        ctx_out = (float*)d_out;
        scores_out = (float*)d_out + CTX_ELEMS;
    } else if (out_size == SCORES_ELEMS) {
        scores_out = (float*)d_out;
        ctx_out = cfb;
    } else {
        ctx_out = (float*)d_out;
        scores_out = sfb;
    }

    cudaFuncSetAttribute(proj_mma_kernel,
                         cudaFuncAttributeMaxDynamicSharedMemorySize, MMA_SMEM_BYTES);
    cudaFuncSetAttribute(fused_attn_kernel,
                         cudaFuncAttributeMaxDynamicSharedMemorySize, FUSED_SMEM_BYTES);

    dim3 pg(8, 32);  // N/128, M/128
    proj_mma_kernel<<<pg, 256, MMA_SMEM_BYTES>>>(qx, Wq, bq, qp);
    proj_mma_kernel<<<pg, 256, MMA_SMEM_BYTES>>>(kx, Wk, bk, kp);
    proj_mma_kernel<<<pg, 256, MMA_SMEM_BYTES>>>(vx, Wv, bv, vp);
    fused_attn_kernel<<<dim3(8, BH), 256, FUSED_SMEM_BYTES>>>(
        qp, kp, vp, mask, scores_out, ctx_out);
}